// round 1
// baseline (speedup 1.0000x reference)
#include <cuda_runtime.h>
#include <stdint.h>

// PaddingJacobiens: pure gather/permutation with zero fill.
// Input:  (32, 64, 64, 64) NHWC float32  (33.5 MB)
// Output: (32, 192, 192, 64) float32     (302 MB)
//
// Derivation from the reference (raw reshapes collapse to index math):
//   m (per-batch linear out idx) = ci*36864 + rr*192 + ss,  ci<64, rr,ss<192
//   i = rr/3 + rr%3 ; j = ss/3 + ss%3          (im2col, K=3, S=1)
//   n = ci*4356 + i*66 + j                     (66 = H + 2*pad; 4356 = 66*66)
//   p = n/64 ; ch = n%64 ; r = p/66 ; c = p%66 (channel-scrambling reshape)
//   out = (1<=r<=64 && 1<=c<=64) ? in[b, r-1, c-1, ch] : 0
//
// Per-batch input address when inside = (r-1)*4096 + (c-1)*64 + ch
//                                     = n - 128*r - 4160   (nearly linear in n)
// => reads are localized & L2-resident; writes (in m order) fully coalesced.
// Kernel is HBM-write bound: ~302 MB store + ~34 MB load.

static constexpr int B        = 32;
static constexpr int C        = 64;
static constexpr int OUTHW    = 192;               // out1*K = out2*K
static constexpr int PER_B_EL = C * OUTHW * OUTHW; // 2359296
static constexpr int PER_B_V4 = PER_B_EL / 4;      // 589824
static constexpr int TOTAL_V4 = B * PER_B_V4;      // 18874368

__global__ __launch_bounds__(256)
void pj_gather_kernel(const float* __restrict__ in, float4* __restrict__ out)
{
    unsigned v = blockIdx.x * 256u + threadIdx.x;
    if (v >= (unsigned)TOTAL_V4) return;

    // Decompose vector index: v = ((b*64 + ci)*192 + rr)*48 + sblk
    unsigned b    = v / (unsigned)PER_B_V4;
    unsigned rem  = v - b * (unsigned)PER_B_V4;
    unsigned ci   = rem / 9216u;          // 192*48
    rem          -= ci * 9216u;
    unsigned rr   = rem / 48u;
    unsigned sblk = rem - rr * 48u;
    unsigned ss0  = sblk * 4u;

    unsigned i     = rr / 3u + rr % 3u;
    unsigned nbase = ci * 4356u + i * 66u;

    const float* __restrict__ inb = in + (size_t)b * (64u * 64u * 64u);

    float vals[4];
#pragma unroll
    for (int e = 0; e < 4; ++e) {
        unsigned ss = ss0 + (unsigned)e;
        unsigned j  = ss / 3u + ss % 3u;
        unsigned n  = nbase + j;
        unsigned p  = n >> 6;       // n / 64
        unsigned ch = n & 63u;      // n % 64
        unsigned r  = p / 66u;
        unsigned c  = p - r * 66u;

        float val = 0.0f;
        // inside iff 1<=r<=64 && 1<=c<=64
        if ((r - 1u) < 64u && (c - 1u) < 64u) {
            unsigned addr = ((r - 1u) * 64u + (c - 1u)) * 64u + ch;
            val = __ldg(inb + addr);
        }
        vals[e] = val;
    }

    out[v] = make_float4(vals[0], vals[1], vals[2], vals[3]);
}

extern "C" void kernel_launch(void* const* d_in, const int* in_sizes, int n_in,
                              void* d_out, int out_size)
{
    (void)in_sizes; (void)n_in; (void)out_size;
    const float* in = (const float*)d_in[0];
    float4* out = (float4*)d_out;

    const int threads = 256;
    const int blocks  = (TOTAL_V4 + threads - 1) / threads; // 73728
    pj_gather_kernel<<<blocks, threads>>>(in, out);
}

// round 5
// speedup vs baseline: 1.4942x; 1.4942x over previous
#include <cuda_runtime.h>
#include <stdint.h>

// PaddingJacobiens: output (32,192,192,64); per (b,ci) tile the 192x192 output
// is a sliding-window replication of a 66x66 intermediate V:
//   V[i*66+j] = (1<=r<=64 && 1<=c<=64) ? in[n - 128*r - 4160] : 0
//     where n = ci*4356 + i*66 + j, p=n>>6, r=p/66, c=p%66
//   out[rr][ss] = V[i(rr)*66 + j(ss)], i=rr/3+rr%3, j=ss/3+ss%3
//
// Per-(b,ci) block, three stages:
//   1. gather V (4356 floats) global -> shared
//   2. expand rows: E[i][3q+t] = V[i][q+t] (t=0..2) -> E is 66x192 floats
//   3. output row rr = verbatim float4 copy of E[i(rr)]; with 384 threads the
//      stride covers exactly 8 rows, so col is fixed per thread and the inner
//      loop is LDS(itab broadcast) + LDS.128 + STG.128 only.

static constexpr int THREADS  = 384;
static constexpr int OUT_V4   = 9216;          // 192*192/4 per tile
static constexpr int E_V4     = 66 * 48;       // 3168 float4 (50688 B)
static constexpr int V_FLOATS = 4356;          // 66*66
static constexpr int SMEM_BYTES = E_V4 * 16 + V_FLOATS * 4 + 192 * 4; // 68880

__global__ __launch_bounds__(THREADS)
void pj_tile_kernel(const float* __restrict__ in, float4* __restrict__ out)
{
    extern __shared__ float4 smem4[];
    float4*   __restrict__ E4   = smem4;                           // [66][48] f4
    float*    __restrict__ E    = reinterpret_cast<float*>(smem4); // [66][192]
    float*    __restrict__ V    = reinterpret_cast<float*>(smem4 + E_V4); // 4356
    unsigned* __restrict__ itab = reinterpret_cast<unsigned*>(V + V_FLOATS); // 192

    const unsigned tile = blockIdx.x;        // b*64 + ci
    const unsigned ci   = tile & 63u;
    const unsigned b    = tile >> 6;
    const unsigned tid  = threadIdx.x;

    const float* __restrict__ inb = in + (size_t)b * 262144u; // 64*64*64
    const unsigned nbase = ci * 4356u;

    // ---- itab: rr -> i(rr)*48 ----
    if (tid < 192u) {
        unsigned u = tid / 3u;
        unsigned s = tid - 3u * u;
        itab[tid] = (u + s) * 48u;
    }

    // ---- Phase 1: gather 66x66 tile into shared ----
    #pragma unroll
    for (unsigned idx = tid; idx < (unsigned)V_FLOATS; idx += THREADS) {
        unsigned n  = nbase + idx;
        unsigned p  = n >> 6;
        unsigned r  = (p * 15888u) >> 20;   // exact p/66 for p < 32768
        unsigned c  = p - r * 66u;
        float val = 0.0f;
        if ((r - 1u) < 64u && (c - 1u) < 64u) {
            val = __ldg(inb + (n - 128u * r - 4160u));
        }
        V[idx] = val;
    }
    __syncthreads();

    // ---- Phase 1.5: expand V rows (66) to E rows (192) ----
    // E[row][3q+t] = V[row][q+t]; 4224 items = 11 exact iterations
    #pragma unroll
    for (unsigned wi = tid; wi < 4224u; wi += THREADS) {
        unsigned row = wi >> 6;             // /64
        unsigned q   = wi & 63u;
        const float* vr = V + row * 66u + q;
        float v0 = vr[0], v1 = vr[1], v2 = vr[2];
        float* er = E + row * 192u + 3u * q;
        er[0] = v0; er[1] = v1; er[2] = v2;
    }
    __syncthreads();

    // ---- Phase 2: verbatim row copies, float4; 24 exact iterations ----
    float4* __restrict__ outt = out + (size_t)tile * OUT_V4;
    const unsigned col = tid % 48u;          // fixed per thread
    unsigned rr        = tid / 48u;          // advances by 8 per iter

    #pragma unroll 6
    for (unsigned t = tid; t < (unsigned)OUT_V4; t += THREADS, rr += 8u) {
        outt[t] = E4[itab[rr] + col];
    }
}

extern "C" void kernel_launch(void* const* d_in, const int* in_sizes, int n_in,
                              void* d_out, int out_size)
{
    (void)in_sizes; (void)n_in; (void)out_size;
    const float* in = (const float*)d_in[0];
    float4* out = (float4*)d_out;

    // Idempotent, not stream-ordered, capture-safe.
    cudaFuncSetAttribute(pj_tile_kernel,
                         cudaFuncAttributeMaxDynamicSharedMemorySize,
                         SMEM_BYTES);

    pj_tile_kernel<<<2048, THREADS, SMEM_BYTES>>>(in, out); // one block per (b,ci)
}

// round 7
// speedup vs baseline: 1.6108x; 1.0781x over previous
#include <cuda_runtime.h>
#include <stdint.h>

// PaddingJacobiens: output (32,192,192,64); per (b,ci) tile the 192x192 output
// is a sliding-window replication of a 66x66 virtual tile V:
//   V[i][j] = (1<=r<=64 && 1<=c<=64) ? in[n - 128*r - 4160] : 0
//     where n = ci*4356 + i*66 + j, p=n>>6, r=p/66, c=p%66
//   out[rr][ss] = V[i(rr)][j(ss)], i=rr/3+rr%3, j=ss/3+ss%3
//
// Per-(b,ci) block, two stages (gather+expand fused):
//   A. E[row][3q+t] = V[row][q+t] (t=0..2), gathered straight from global.
//      The three loads per item are consecutive addresses -> coalesced, and the
//      3x overlap across t is L1-served. No V staging buffer, one less sync.
//   B. output row rr = verbatim float4 streaming-store copy of E[i(rr)].
// smem = 51.5 KB -> 4 CTAs/SM for better phase overlap on the store stream.

static constexpr int THREADS  = 384;
static constexpr int OUT_V4   = 9216;          // 192*192/4 per tile
static constexpr int E_V4     = 66 * 48;       // 3168 float4 (50688 B)
static constexpr int SMEM_BYTES = E_V4 * 16 + 192 * 4; // 51456

__global__ __launch_bounds__(THREADS)
void pj_tile_kernel(const float* __restrict__ in, float4* __restrict__ out)
{
    extern __shared__ float4 smem4[];
    float4*   __restrict__ E4   = smem4;                           // [66][48] f4
    float*    __restrict__ E    = reinterpret_cast<float*>(smem4); // [66][192]
    unsigned* __restrict__ itab = reinterpret_cast<unsigned*>(smem4 + E_V4);

    const unsigned tile = blockIdx.x;        // b*64 + ci
    const unsigned ci   = tile & 63u;
    const unsigned b    = tile >> 6;
    const unsigned tid  = threadIdx.x;

    const float* __restrict__ inb = in + (size_t)b * 262144u; // 64*64*64
    const unsigned nbase = ci * 4356u;

    // ---- itab: rr -> i(rr)*48 ----
    if (tid < 192u) {
        unsigned u = tid / 3u;
        unsigned s = tid - 3u * u;
        itab[tid] = (u + s) * 48u;
    }

    // ---- Phase A: fused gather + row expansion ----
    // 4224 items (66 rows x 64 q-positions) = 11 exact iterations
    #pragma unroll
    for (unsigned wi = tid; wi < 4224u; wi += THREADS) {
        unsigned row = wi >> 6;             // /64
        unsigned q   = wi & 63u;
        unsigned nb  = nbase + row * 66u + q;
        float*   er  = E + row * 192u + 3u * q;
        #pragma unroll
        for (unsigned t = 0; t < 3u; ++t) {
            unsigned n = nb + t;
            unsigned p = n >> 6;
            unsigned r = (p * 15888u) >> 20;  // exact p/66 for p < 32768
            unsigned c = p - r * 66u;
            float val = 0.0f;
            if ((r - 1u) < 64u && (c - 1u) < 64u) {
                val = __ldg(inb + (n - 128u * r - 4160u));
            }
            er[t] = val;
        }
    }
    __syncthreads();

    // ---- Phase B: verbatim row copies, streaming float4 stores ----
    // 24 exact iterations; col fixed per thread, row advances by 8
    float4* __restrict__ outt = out + (size_t)tile * OUT_V4;
    const unsigned col = tid % 48u;
    unsigned rr        = tid / 48u;

    #pragma unroll 6
    for (unsigned t = tid; t < (unsigned)OUT_V4; t += THREADS, rr += 8u) {
        __stcs(&outt[t], E4[itab[rr] + col]);
    }
}

extern "C" void kernel_launch(void* const* d_in, const int* in_sizes, int n_in,
                              void* d_out, int out_size)
{
    (void)in_sizes; (void)n_in; (void)out_size;
    const float* in = (const float*)d_in[0];
    float4* out = (float4*)d_out;

    // Idempotent, not stream-ordered, capture-safe.
    cudaFuncSetAttribute(pj_tile_kernel,
                         cudaFuncAttributeMaxDynamicSharedMemorySize,
                         SMEM_BYTES);

    pj_tile_kernel<<<2048, THREADS, SMEM_BYTES>>>(in, out); // one block per (b,ci)
}